// round 3
// baseline (speedup 1.0000x reference)
#include <cuda_runtime.h>
#include <cuda_bf16.h>
#include <math_constants.h>

// Problem constants
#define N_NODES   50000
#define N_EDGES   800000
#define IN_FEATS  256
#define EDGE_FEATS 64
#define NUM_HEADS 4
#define OUT_FEATS 32
#define HF        128           // NUM_HEADS*OUT_FEATS
#define QCOLS     256           // NUM_HEADS*EDGE_FEATS

#define SCAN_BLK  512
#define NB_SCAN   ((N_NODES + SCAN_BLK - 1) / SCAN_BLK)   // 98

// Scratch (static device globals; no allocation allowed)
__device__ float g_h[N_NODES * HF];          // projected node feats  [N,128]
__device__ float g_q[N_NODES * QCOLS];       // q[n,h,k]  [N,4,64]  pre-scaled by 1/sqrt(32)
__device__ int   g_cnt[N_NODES];             // in-degree histogram
__device__ int   g_off[N_NODES + 1];         // CSR offsets (by dst)
__device__ int   g_cur[N_NODES];             // scatter cursors
__device__ float g_w[N_EDGES * NUM_HEADS];   // exp(score) grouped by dst (CSR order)
__device__ int   g_psrc[N_EDGES];            // src node id, grouped by dst (CSR order)
__device__ int   g_part[NB_SCAN];            // scan block sums
__device__ int   g_partx[NB_SCAN];           // scan block prefix (exclusive)

// ---------------------------------------------------------------------------
__global__ void zero_cnt_kernel() {
    int i = blockIdx.x * blockDim.x + threadIdx.x;
    if (i < N_NODES) g_cnt[i] = 0;
}

// ---------------------------------------------------------------------------
// K1: h = node_feat[N,256] @ W_node[256,128]  (register-blocked SGEMM)
// ---------------------------------------------------------------------------
__global__ __launch_bounds__(256) void gemm_node_kernel(
    const float* __restrict__ A, const float* __restrict__ B) {
    __shared__ float As[32][64];   // transposed A tile: As[k][m]
    __shared__ float Bs[32][128];

    const int tid = threadIdx.x;
    const int block_m = blockIdx.x * 64;
    const int tcol = (tid & 31) * 4;
    const int trow = (tid >> 5) * 8;

    float acc[8][4];
#pragma unroll
    for (int i = 0; i < 8; i++)
#pragma unroll
        for (int j = 0; j < 4; j++) acc[i][j] = 0.0f;

    for (int k0 = 0; k0 < IN_FEATS; k0 += 32) {
#pragma unroll
        for (int i = 0; i < 2; i++) {
            int idx = tid + i * 256;
            int row = idx >> 3;
            int kk  = (idx & 7) * 4;
            float4 v = make_float4(0.f, 0.f, 0.f, 0.f);
            int grow = block_m + row;
            if (grow < N_NODES)
                v = *(const float4*)&A[grow * IN_FEATS + k0 + kk];
            As[kk + 0][row] = v.x; As[kk + 1][row] = v.y;
            As[kk + 2][row] = v.z; As[kk + 3][row] = v.w;
        }
#pragma unroll
        for (int i = 0; i < 4; i++) {
            int idx = tid + i * 256;
            int row = idx >> 5;
            int cc  = (idx & 31) * 4;
            *(float4*)&Bs[row][cc] = *(const float4*)&B[(k0 + row) * HF + cc];
        }
        __syncthreads();

#pragma unroll
        for (int kk = 0; kk < 32; kk++) {
            float a[8];
#pragma unroll
            for (int i = 0; i < 8; i++) a[i] = As[kk][trow + i];
            float4 bv = *(float4*)&Bs[kk][tcol];
#pragma unroll
            for (int i = 0; i < 8; i++) {
                acc[i][0] += a[i] * bv.x;
                acc[i][1] += a[i] * bv.y;
                acc[i][2] += a[i] * bv.z;
                acc[i][3] += a[i] * bv.w;
            }
        }
        __syncthreads();
    }

#pragma unroll
    for (int i = 0; i < 8; i++) {
        int grow = block_m + trow + i;
        if (grow < N_NODES) {
            float4 v = make_float4(acc[i][0], acc[i][1], acc[i][2], acc[i][3]);
            *(float4*)&g_h[grow * HF + tcol] = v;
        }
    }
}

// ---------------------------------------------------------------------------
// K2: q[n,h,k] = (1/sqrt(32)) * sum_f h[n,h*32+f] * W_edge[k, h*32+f]
// ---------------------------------------------------------------------------
__global__ __launch_bounds__(256) void make_q_kernel(const float* __restrict__ We) {
    __shared__ float WeT[HF * EDGE_FEATS];   // WeT[c*64 + k] = We[k*128 + c]
    __shared__ float hs[4][HF];

    const int tid = threadIdx.x;
    for (int i = tid; i < EDGE_FEATS * HF; i += 256) {
        int k = i >> 7, c = i & 127;
        WeT[c * EDGE_FEATS + k] = We[i];
    }

    const int hh = tid >> 6;
    const int k  = tid & 63;
    const int node0 = blockIdx.x * 16;
    const float scale = 0.17677669529663687f;   // 1/sqrt(32)

    for (int g = 0; g < 4; g++) {
        __syncthreads();
        for (int i = tid; i < 4 * HF; i += 256) {
            int ni = i >> 7, c = i & 127;
            int n = node0 + g * 4 + ni;
            hs[ni][c] = (n < N_NODES) ? g_h[n * HF + c] : 0.0f;
        }
        __syncthreads();

        float acc[4] = {0.f, 0.f, 0.f, 0.f};
#pragma unroll
        for (int f = 0; f < OUT_FEATS; f++) {
            float w = WeT[(hh * OUT_FEATS + f) * EDGE_FEATS + k];
#pragma unroll
            for (int ni = 0; ni < 4; ni++) acc[ni] += hs[ni][hh * OUT_FEATS + f] * w;
        }
#pragma unroll
        for (int ni = 0; ni < 4; ni++) {
            int n = node0 + g * 4 + ni;
            if (n < N_NODES)
                g_q[(n * NUM_HEADS + hh) * EDGE_FEATS + k] = acc[ni] * scale;
        }
    }
}

// ---------------------------------------------------------------------------
// CSR build: histogram -> scan (3 kernels)
// ---------------------------------------------------------------------------
__global__ void hist_kernel(const int* __restrict__ dst) {
    int e = blockIdx.x * blockDim.x + threadIdx.x;
    if (e < N_EDGES) atomicAdd(&g_cnt[dst[e]], 1);
}

__global__ __launch_bounds__(SCAN_BLK) void scan1_kernel() {
    __shared__ int sm[SCAN_BLK];
    int t = threadIdx.x;
    int i = blockIdx.x * SCAN_BLK + t;
    sm[t] = (i < N_NODES) ? g_cnt[i] : 0;
    __syncthreads();
    for (int off = SCAN_BLK / 2; off > 0; off >>= 1) {
        if (t < off) sm[t] += sm[t + off];
        __syncthreads();
    }
    if (t == 0) g_part[blockIdx.x] = sm[0];
}

__global__ __launch_bounds__(128) void scan2_kernel() {
    __shared__ int sm[2][128];
    int t = threadIdx.x;
    int v = (t < NB_SCAN) ? g_part[t] : 0;
    int pi = 0;
    sm[0][t] = v;
    __syncthreads();
#pragma unroll
    for (int off = 1; off < 128; off <<= 1) {
        int add = (t >= off) ? sm[pi][t - off] : 0;
        sm[pi ^ 1][t] = sm[pi][t] + add;
        pi ^= 1;
        __syncthreads();
    }
    if (t < NB_SCAN) g_partx[t] = sm[pi][t] - v;   // exclusive
}

__global__ __launch_bounds__(SCAN_BLK) void scan3_kernel() {
    __shared__ int sm[2][SCAN_BLK];
    int t = threadIdx.x;
    int i = blockIdx.x * SCAN_BLK + t;
    int v = (i < N_NODES) ? g_cnt[i] : 0;
    int pi = 0;
    sm[0][t] = v;
    __syncthreads();
#pragma unroll
    for (int off = 1; off < SCAN_BLK; off <<= 1) {
        int add = (t >= off) ? sm[pi][t - off] : 0;
        sm[pi ^ 1][t] = sm[pi][t] + add;
        pi ^= 1;
        __syncthreads();
    }
    if (i < N_NODES) {
        int excl = g_partx[blockIdx.x] + sm[pi][t] - v;
        g_off[i] = excl;
        g_cur[i] = excl;
    }
    if (blockIdx.x == 0 && t == 0) g_off[N_NODES] = N_EDGES;
}

// ---------------------------------------------------------------------------
// score_scatter: warp per edge.
//   lane l: head h = l>>3, k-chunk k0 = (l&7)*8
//   w[h] = exp(leaky(sum_k ef[e,k]*q[src,h,k]))   (no max needed; scores small)
//   Scatter w + src into dst-CSR slot (cursor atomicAdd).
// ---------------------------------------------------------------------------
__global__ __launch_bounds__(256) void score_scatter_kernel(
    const float* __restrict__ ef, const int* __restrict__ src,
    const int* __restrict__ dst) {
    const int e = (blockIdx.x * 256 + threadIdx.x) >> 5;
    if (e >= N_EDGES) return;
    const int lane = threadIdx.x & 31;
    const int h  = lane >> 3;
    const int k0 = (lane & 7) * 8;

    const int s = __ldg(&src[e]);
    const int d = __ldg(&dst[e]);

    const float4 ef0 = *(const float4*)(ef + (size_t)e * EDGE_FEATS + k0);
    const float4 ef1 = *(const float4*)(ef + (size_t)e * EDGE_FEATS + k0 + 4);
    const float* qp = g_q + (size_t)s * QCOLS + h * EDGE_FEATS + k0;
    const float4 q0 = *(const float4*)qp;
    const float4 q1 = *(const float4*)(qp + 4);

    float p = ef0.x * q0.x + ef0.y * q0.y + ef0.z * q0.z + ef0.w * q0.w
            + ef1.x * q1.x + ef1.y * q1.y + ef1.z * q1.z + ef1.w * q1.w;
    p += __shfl_xor_sync(0xffffffffu, p, 1);
    p += __shfl_xor_sync(0xffffffffu, p, 2);
    p += __shfl_xor_sync(0xffffffffu, p, 4);

    const float sc = (p > 0.0f) ? p : 0.01f * p;   // leaky relu
    const float w = __expf(sc);

    int pos;
    if (lane == 0) pos = atomicAdd(&g_cur[d], 1);
    pos = __shfl_sync(0xffffffffu, pos, 0);

    if ((lane & 7) == 0) g_w[pos * NUM_HEADS + h] = w;
    if (lane == 0) g_psrc[pos] = s;
}

// ---------------------------------------------------------------------------
// agg: warp per dst node. out[d] = (sum_j w_j * h[src_j]) / (sum_j w_j)
// lane l: head h = l>>3, features [4l, 4l+4)
// ---------------------------------------------------------------------------
__global__ __launch_bounds__(256) void agg_kernel(float* __restrict__ out) {
    const int d = (blockIdx.x * 256 + threadIdx.x) >> 5;
    if (d >= N_NODES) return;
    const int lane = threadIdx.x & 31;
    const int h = lane >> 3;

    const int beg = __ldg(&g_off[d]);
    const int end = __ldg(&g_off[d + 1]);

    float den = 0.0f;
    float4 acc = make_float4(0.f, 0.f, 0.f, 0.f);

    // one-ahead prefetch of (w, psrc) so dependent hv load pipelines
    float w = 0.0f;
    int ps = 0;
    if (beg < end) {
        w  = __ldg(&g_w[beg * NUM_HEADS + h]);
        ps = __ldg(&g_psrc[beg]);
    }

    for (int j = beg; j < end; j++) {
        const float w_c = w;
        const int ps_c = ps;
        if (j + 1 < end) {
            w  = __ldg(&g_w[(j + 1) * NUM_HEADS + h]);
            ps = __ldg(&g_psrc[j + 1]);
        }
        const float4 hv = *(const float4*)(g_h + (size_t)ps_c * HF + lane * 4);
        den += w_c;
        acc.x += w_c * hv.x;
        acc.y += w_c * hv.y;
        acc.z += w_c * hv.z;
        acc.w += w_c * hv.w;
    }

    const float inv = (den > 0.0f) ? __frcp_rn(den) : 0.0f;
    float4 o = make_float4(acc.x * inv, acc.y * inv, acc.z * inv, acc.w * inv);
    *(float4*)(out + (size_t)d * HF + lane * 4) = o;
}

// ---------------------------------------------------------------------------
extern "C" void kernel_launch(void* const* d_in, const int* in_sizes, int n_in,
                              void* d_out, int out_size) {
    const float* node_feat = (const float*)d_in[0];
    const float* edge_feat = (const float*)d_in[1];
    const int*   src       = (const int*)d_in[2];
    const int*   dst       = (const int*)d_in[3];
    const float* W_node    = (const float*)d_in[4];
    const float* W_edge    = (const float*)d_in[5];
    float* out = (float*)d_out;

    zero_cnt_kernel<<<(N_NODES + 255) / 256, 256>>>();
    gemm_node_kernel<<<(N_NODES + 63) / 64, 256>>>(node_feat, W_node);
    make_q_kernel<<<(N_NODES + 15) / 16, 256>>>(W_edge);
    hist_kernel<<<(N_EDGES + 255) / 256, 256>>>(dst);
    scan1_kernel<<<NB_SCAN, SCAN_BLK>>>();
    scan2_kernel<<<1, 128>>>();
    scan3_kernel<<<NB_SCAN, SCAN_BLK>>>();
    score_scatter_kernel<<<(N_EDGES * 32 + 255) / 256, 256>>>(edge_feat, src, dst);
    agg_kernel<<<(N_NODES * 32 + 255) / 256, 256>>>(out);
}

// round 4
// speedup vs baseline: 1.1434x; 1.1434x over previous
#include <cuda_runtime.h>
#include <cuda_bf16.h>
#include <cuda_fp16.h>
#include <math_constants.h>

// Problem constants
#define N_NODES   50000
#define N_EDGES   800000
#define IN_FEATS  256
#define EDGE_FEATS 64
#define NUM_HEADS 4
#define OUT_FEATS 32
#define HF        128           // NUM_HEADS*OUT_FEATS
#define QCOLS     256           // NUM_HEADS*EDGE_FEATS

#define SCAN_BLK  512
#define NB_SCAN   ((N_NODES + SCAN_BLK - 1) / SCAN_BLK)   // 98

// Scratch (static device globals; no allocation allowed)
__device__ float  g_h[N_NODES * HF];          // projected node feats  [N,128] fp32
__device__ __half g_qh[N_NODES * QCOLS];      // q[n,h,k] fp16, pre-scaled by 1/sqrt(32)
__device__ int    g_cnt[N_NODES];             // in-degree histogram
__device__ int    g_off[N_NODES + 1];         // CSR offsets (by dst)
__device__ int    g_cur[N_NODES];             // scatter cursors
__device__ int    g_eid[N_EDGES];             // edge id grouped by dst
__device__ int    g_psrc[N_EDGES];            // src id grouped by dst
__device__ int    g_part[NB_SCAN];
__device__ int    g_partx[NB_SCAN];

// ---------------------------------------------------------------------------
__global__ void zero_cnt_kernel() {
    int i = blockIdx.x * blockDim.x + threadIdx.x;
    if (i < N_NODES) g_cnt[i] = 0;
}

// ---------------------------------------------------------------------------
// K1: h = node_feat[N,256] @ W_node[256,128]  (register-blocked SGEMM)
// ---------------------------------------------------------------------------
__global__ __launch_bounds__(256) void gemm_node_kernel(
    const float* __restrict__ A, const float* __restrict__ B) {
    __shared__ float As[32][64];   // transposed A tile: As[k][m]
    __shared__ float Bs[32][128];

    const int tid = threadIdx.x;
    const int block_m = blockIdx.x * 64;
    const int tcol = (tid & 31) * 4;
    const int trow = (tid >> 5) * 8;

    float acc[8][4];
#pragma unroll
    for (int i = 0; i < 8; i++)
#pragma unroll
        for (int j = 0; j < 4; j++) acc[i][j] = 0.0f;

    for (int k0 = 0; k0 < IN_FEATS; k0 += 32) {
#pragma unroll
        for (int i = 0; i < 2; i++) {
            int idx = tid + i * 256;
            int row = idx >> 3;
            int kk  = (idx & 7) * 4;
            float4 v = make_float4(0.f, 0.f, 0.f, 0.f);
            int grow = block_m + row;
            if (grow < N_NODES)
                v = *(const float4*)&A[grow * IN_FEATS + k0 + kk];
            As[kk + 0][row] = v.x; As[kk + 1][row] = v.y;
            As[kk + 2][row] = v.z; As[kk + 3][row] = v.w;
        }
#pragma unroll
        for (int i = 0; i < 4; i++) {
            int idx = tid + i * 256;
            int row = idx >> 5;
            int cc  = (idx & 31) * 4;
            *(float4*)&Bs[row][cc] = *(const float4*)&B[(k0 + row) * HF + cc];
        }
        __syncthreads();

#pragma unroll
        for (int kk = 0; kk < 32; kk++) {
            float a[8];
#pragma unroll
            for (int i = 0; i < 8; i++) a[i] = As[kk][trow + i];
            float4 bv = *(float4*)&Bs[kk][tcol];
#pragma unroll
            for (int i = 0; i < 8; i++) {
                acc[i][0] += a[i] * bv.x;
                acc[i][1] += a[i] * bv.y;
                acc[i][2] += a[i] * bv.z;
                acc[i][3] += a[i] * bv.w;
            }
        }
        __syncthreads();
    }

#pragma unroll
    for (int i = 0; i < 8; i++) {
        int grow = block_m + trow + i;
        if (grow < N_NODES) {
            float4 v = make_float4(acc[i][0], acc[i][1], acc[i][2], acc[i][3]);
            *(float4*)&g_h[grow * HF + tcol] = v;
        }
    }
}

// ---------------------------------------------------------------------------
// K2: q[n,h,k] = (1/sqrt(32)) * sum_f h[n,h*32+f] * W_edge[k, h*32+f]
// Computed fp32, stored fp16 (single rounding).
// ---------------------------------------------------------------------------
__global__ __launch_bounds__(256) void make_q_kernel(const float* __restrict__ We) {
    __shared__ float WeT[HF * EDGE_FEATS];   // WeT[c*64 + k] = We[k*128 + c]
    __shared__ float hs[4][HF];

    const int tid = threadIdx.x;
    for (int i = tid; i < EDGE_FEATS * HF; i += 256) {
        int k = i >> 7, c = i & 127;
        WeT[c * EDGE_FEATS + k] = We[i];
    }

    const int hh = tid >> 6;
    const int k  = tid & 63;
    const int node0 = blockIdx.x * 16;
    const float scale = 0.17677669529663687f;   // 1/sqrt(32)

    for (int g = 0; g < 4; g++) {
        __syncthreads();
        for (int i = tid; i < 4 * HF; i += 256) {
            int ni = i >> 7, c = i & 127;
            int n = node0 + g * 4 + ni;
            hs[ni][c] = (n < N_NODES) ? g_h[n * HF + c] : 0.0f;
        }
        __syncthreads();

        float acc[4] = {0.f, 0.f, 0.f, 0.f};
#pragma unroll
        for (int f = 0; f < OUT_FEATS; f++) {
            float w = WeT[(hh * OUT_FEATS + f) * EDGE_FEATS + k];
#pragma unroll
            for (int ni = 0; ni < 4; ni++) acc[ni] += hs[ni][hh * OUT_FEATS + f] * w;
        }
#pragma unroll
        for (int ni = 0; ni < 4; ni++) {
            int n = node0 + g * 4 + ni;
            if (n < N_NODES)
                g_qh[(n * NUM_HEADS + hh) * EDGE_FEATS + k] = __float2half_rn(acc[ni] * scale);
        }
    }
}

// ---------------------------------------------------------------------------
// CSR build: histogram -> scan (3 kernels) -> scatter (eid + psrc)
// ---------------------------------------------------------------------------
__global__ void hist_kernel(const int* __restrict__ dst) {
    int e = blockIdx.x * blockDim.x + threadIdx.x;
    if (e < N_EDGES) atomicAdd(&g_cnt[dst[e]], 1);
}

__global__ __launch_bounds__(SCAN_BLK) void scan1_kernel() {
    __shared__ int sm[SCAN_BLK];
    int t = threadIdx.x;
    int i = blockIdx.x * SCAN_BLK + t;
    sm[t] = (i < N_NODES) ? g_cnt[i] : 0;
    __syncthreads();
    for (int off = SCAN_BLK / 2; off > 0; off >>= 1) {
        if (t < off) sm[t] += sm[t + off];
        __syncthreads();
    }
    if (t == 0) g_part[blockIdx.x] = sm[0];
}

__global__ __launch_bounds__(128) void scan2_kernel() {
    __shared__ int sm[2][128];
    int t = threadIdx.x;
    int v = (t < NB_SCAN) ? g_part[t] : 0;
    int pi = 0;
    sm[0][t] = v;
    __syncthreads();
#pragma unroll
    for (int off = 1; off < 128; off <<= 1) {
        int add = (t >= off) ? sm[pi][t - off] : 0;
        sm[pi ^ 1][t] = sm[pi][t] + add;
        pi ^= 1;
        __syncthreads();
    }
    if (t < NB_SCAN) g_partx[t] = sm[pi][t] - v;   // exclusive
}

__global__ __launch_bounds__(SCAN_BLK) void scan3_kernel() {
    __shared__ int sm[2][SCAN_BLK];
    int t = threadIdx.x;
    int i = blockIdx.x * SCAN_BLK + t;
    int v = (i < N_NODES) ? g_cnt[i] : 0;
    int pi = 0;
    sm[0][t] = v;
    __syncthreads();
#pragma unroll
    for (int off = 1; off < SCAN_BLK; off <<= 1) {
        int add = (t >= off) ? sm[pi][t - off] : 0;
        sm[pi ^ 1][t] = sm[pi][t] + add;
        pi ^= 1;
        __syncthreads();
    }
    if (i < N_NODES) {
        int excl = g_partx[blockIdx.x] + sm[pi][t] - v;
        g_off[i] = excl;
        g_cur[i] = excl;
    }
    if (blockIdx.x == 0 && t == 0) g_off[N_NODES] = N_EDGES;
}

__global__ void scatter_kernel(const int* __restrict__ src, const int* __restrict__ dst) {
    int e = blockIdx.x * blockDim.x + threadIdx.x;
    if (e < N_EDGES) {
        int pos = atomicAdd(&g_cur[dst[e]], 1);
        g_eid[pos]  = e;
        g_psrc[pos] = src[e];
    }
}

// ---------------------------------------------------------------------------
// Fused: warp per dst node, NO max subtraction (scores are O(1), softmax is
// shift-invariant). lane l: head h=l>>3, k-chunk k0=(l&7)*8.
//   w[h] = exp(leaky(sum_k ef[e,k]*q[src,h,k]))
//   out[d] = (sum_e w*h[src]) / (sum_e w)
// Accumulation is plain FMAs — no cross-edge serial dependency.
// ---------------------------------------------------------------------------
__global__ __launch_bounds__(256) void fused_kernel(
    const float* __restrict__ ef, float* __restrict__ out) {
    const int d = (blockIdx.x * 256 + threadIdx.x) >> 5;
    if (d >= N_NODES) return;
    const int lane = threadIdx.x & 31;
    const int h  = lane >> 3;
    const int k0 = (lane & 7) * 8;

    const int beg = __ldg(&g_off[d]);
    const int end = __ldg(&g_off[d + 1]);

    float den = 0.0f;
    float4 acc = make_float4(0.f, 0.f, 0.f, 0.f);

    // one-ahead prefetch of index pair
    int eid = 0, s = 0;
    if (beg < end) {
        eid = __ldg(&g_eid[beg]);
        s   = __ldg(&g_psrc[beg]);
    }

    for (int j = beg; j < end; j++) {
        const int eid_c = eid;
        const int s_c = s;
        if (j + 1 < end) {
            eid = __ldg(&g_eid[j + 1]);
            s   = __ldg(&g_psrc[j + 1]);
        }

        // edge feature chunk (coalesced 256B per warp, 4x lane-group replication)
        const float4 ef0 = *(const float4*)(ef + (size_t)eid_c * EDGE_FEATS + k0);
        const float4 ef1 = *(const float4*)(ef + (size_t)eid_c * EDGE_FEATS + k0 + 4);

        // q chunk: 8 halves = one LDG.128 per lane (512B per warp)
        const uint4 qv = *(const uint4*)(g_qh + (size_t)s_c * QCOLS + h * EDGE_FEATS + k0);
        const float2 q0 = __half22float2(*(const __half2*)&qv.x);
        const float2 q1 = __half22float2(*(((const __half2*)&qv.x) + 1));
        const float2 q2 = __half22float2(*(const __half2*)&qv.z);
        const float2 q3 = __half22float2(*(((const __half2*)&qv.z) + 1));

        float p = ef0.x * q0.x + ef0.y * q0.y + ef0.z * q1.x + ef0.w * q1.y
                + ef1.x * q2.x + ef1.y * q2.y + ef1.z * q3.x + ef1.w * q3.y;
        p += __shfl_xor_sync(0xffffffffu, p, 1);
        p += __shfl_xor_sync(0xffffffffu, p, 2);
        p += __shfl_xor_sync(0xffffffffu, p, 4);
        // every lane in the 8-lane group now holds head h's full score

        const float sc = (p > 0.0f) ? p : 0.01f * p;       // leaky relu
        const float w  = __expf(sc);

        const float4 hv = *(const float4*)(g_h + (size_t)s_c * HF + lane * 4);

        den   += w;
        acc.x += w * hv.x;
        acc.y += w * hv.y;
        acc.z += w * hv.z;
        acc.w += w * hv.w;
    }

    const float inv = (den > 0.0f) ? __frcp_rn(den) : 0.0f;
    float4 o = make_float4(acc.x * inv, acc.y * inv, acc.z * inv, acc.w * inv);
    *(float4*)(out + (size_t)d * HF + lane * 4) = o;
}

// ---------------------------------------------------------------------------
extern "C" void kernel_launch(void* const* d_in, const int* in_sizes, int n_in,
                              void* d_out, int out_size) {
    const float* node_feat = (const float*)d_in[0];
    const float* edge_feat = (const float*)d_in[1];
    const int*   src       = (const int*)d_in[2];
    const int*   dst       = (const int*)d_in[3];
    const float* W_node    = (const float*)d_in[4];
    const float* W_edge    = (const float*)d_in[5];
    float* out = (float*)d_out;

    zero_cnt_kernel<<<(N_NODES + 255) / 256, 256>>>();
    gemm_node_kernel<<<(N_NODES + 63) / 64, 256>>>(node_feat, W_node);
    make_q_kernel<<<(N_NODES + 15) / 16, 256>>>(W_edge);
    hist_kernel<<<(N_EDGES + 255) / 256, 256>>>(dst);
    scan1_kernel<<<NB_SCAN, SCAN_BLK>>>();
    scan2_kernel<<<1, 128>>>();
    scan3_kernel<<<NB_SCAN, SCAN_BLK>>>();
    scatter_kernel<<<(N_EDGES + 255) / 256, 256>>>(src, dst);
    fused_kernel<<<(N_NODES * 32 + 255) / 256, 256>>>(edge_feat, out);
}